// round 3
// baseline (speedup 1.0000x reference)
#include <cuda_runtime.h>
#include <math_constants.h>

// Attention: out = softmax(Q K^T) V, N=4096 tokens, D=1024, fp32.
// 3-kernel materialized-scores design, software-pipelined SGEMMs:
//   K1: S = Q K^T          (SGEMM-NT, 128x128x8 tiles, 8x8 microtile)
//   K2: row softmax on S   (in place, one block per row)
//   K3: out = S V          (SGEMM-NN)
// S lives in a __device__ global (64 MB; allocation-free per harness rules).

#define NTOK 4096
#define DDIM 1024

__device__ float g_S[(size_t)NTOK * (size_t)NTOK];

// ---------------------------------------------------------------------------
// C[M,N] = A[M,K] @ B[N,K]^T      (A, B, C row-major)
// Software-pipelined: global loads for tile k+1 issued before compute of k.
// ---------------------------------------------------------------------------
__global__ __launch_bounds__(256)
void sgemm_nt_kernel(const float* __restrict__ A,
                     const float* __restrict__ B,
                     float* __restrict__ C,
                     int M, int N, int K)
{
    const int BM = 128, BN = 128, BK = 8;
    __shared__ float As[BK][BM + 4];
    __shared__ float Bs[BK][BN + 4];

    const int tid = threadIdx.x;           // 0..255
    const int tx  = tid & 15;              // 16 x 16 thread grid
    const int ty  = tid >> 4;
    const int m0  = blockIdx.y * BM;
    const int n0  = blockIdx.x * BN;

    // global->shared load mapping: 128 rows x 8 cols per tile, float4 per thread
    const int lrow = tid >> 1;             // 0..127
    const int lcol = (tid & 1) * 4;        // 0 or 4
    const float* Ap = A + (size_t)(m0 + lrow) * K + lcol;
    const float* Bp = B + (size_t)(n0 + lrow) * K + lcol;

    float acc[8][8];
#pragma unroll
    for (int i = 0; i < 8; i++)
#pragma unroll
        for (int j = 0; j < 8; j++) acc[i][j] = 0.f;

    // prologue: fetch tile 0 into registers
    float4 a4 = *(const float4*)(Ap);
    float4 b4 = *(const float4*)(Bp);

    for (int k0 = 0; k0 < K; k0 += BK) {
        // store current tile to smem
        As[lcol + 0][lrow] = a4.x;
        As[lcol + 1][lrow] = a4.y;
        As[lcol + 2][lrow] = a4.z;
        As[lcol + 3][lrow] = a4.w;
        Bs[lcol + 0][lrow] = b4.x;
        Bs[lcol + 1][lrow] = b4.y;
        Bs[lcol + 2][lrow] = b4.z;
        Bs[lcol + 3][lrow] = b4.w;
        __syncthreads();

        // prefetch next tile (overlaps with compute below)
        if (k0 + BK < K) {
            a4 = *(const float4*)(Ap + k0 + BK);
            b4 = *(const float4*)(Bp + k0 + BK);
        }

#pragma unroll
        for (int kk = 0; kk < BK; kk++) {
            float4 a0 = *(const float4*)&As[kk][ty * 8];
            float4 a1 = *(const float4*)&As[kk][ty * 8 + 4];
            float4 b0 = *(const float4*)&Bs[kk][tx * 8];
            float4 b1 = *(const float4*)&Bs[kk][tx * 8 + 4];
            float a[8] = {a0.x, a0.y, a0.z, a0.w, a1.x, a1.y, a1.z, a1.w};
            float b[8] = {b0.x, b0.y, b0.z, b0.w, b1.x, b1.y, b1.z, b1.w};
#pragma unroll
            for (int i = 0; i < 8; i++)
#pragma unroll
                for (int j = 0; j < 8; j++)
                    acc[i][j] = fmaf(a[i], b[j], acc[i][j]);
        }
        __syncthreads();
    }

#pragma unroll
    for (int i = 0; i < 8; i++) {
        float* cp = C + (size_t)(m0 + ty * 8 + i) * N + n0 + tx * 8;
        *(float4*)(cp)     = make_float4(acc[i][0], acc[i][1], acc[i][2], acc[i][3]);
        *(float4*)(cp + 4) = make_float4(acc[i][4], acc[i][5], acc[i][6], acc[i][7]);
    }
}

// ---------------------------------------------------------------------------
// C[M,N] = A[M,K] @ B[K,N]        (all row-major)
// ---------------------------------------------------------------------------
__global__ __launch_bounds__(256)
void sgemm_nn_kernel(const float* __restrict__ A,
                     const float* __restrict__ B,
                     float* __restrict__ C,
                     int M, int N, int K)
{
    const int BM = 128, BN = 128, BK = 8;
    __shared__ float As[BK][BM + 4];
    __shared__ float Bs[BK][BN + 4];

    const int tid = threadIdx.x;
    const int tx  = tid & 15;
    const int ty  = tid >> 4;
    const int m0  = blockIdx.y * BM;
    const int n0  = blockIdx.x * BN;

    // A tile: 128 rows x 8 cols (transpose on store)
    const int larow = tid >> 1;
    const int lacol = (tid & 1) * 4;
    const float* Ap = A + (size_t)(m0 + larow) * K + lacol;

    // B tile: 8 rows x 128 cols (direct store)
    const int lbrow = tid >> 5;            // 0..7
    const int lbcol = (tid & 31) * 4;      // 0..124
    const float* Bp = B + (size_t)lbrow * N + n0 + lbcol;

    float acc[8][8];
#pragma unroll
    for (int i = 0; i < 8; i++)
#pragma unroll
        for (int j = 0; j < 8; j++) acc[i][j] = 0.f;

    // prologue: fetch tile 0
    float4 a4 = *(const float4*)(Ap);
    float4 b4 = *(const float4*)(Bp);

    for (int k0 = 0; k0 < K; k0 += BK) {
        As[lacol + 0][larow] = a4.x;
        As[lacol + 1][larow] = a4.y;
        As[lacol + 2][larow] = a4.z;
        As[lacol + 3][larow] = a4.w;
        *(float4*)&Bs[lbrow][lbcol] = b4;
        __syncthreads();

        if (k0 + BK < K) {
            a4 = *(const float4*)(Ap + k0 + BK);
            b4 = *(const float4*)(Bp + (size_t)(k0 + BK) * N);
        }

#pragma unroll
        for (int kk = 0; kk < BK; kk++) {
            float4 a0 = *(const float4*)&As[kk][ty * 8];
            float4 a1 = *(const float4*)&As[kk][ty * 8 + 4];
            float4 b0 = *(const float4*)&Bs[kk][tx * 8];
            float4 b1 = *(const float4*)&Bs[kk][tx * 8 + 4];
            float a[8] = {a0.x, a0.y, a0.z, a0.w, a1.x, a1.y, a1.z, a1.w};
            float b[8] = {b0.x, b0.y, b0.z, b0.w, b1.x, b1.y, b1.z, b1.w};
#pragma unroll
            for (int i = 0; i < 8; i++)
#pragma unroll
                for (int j = 0; j < 8; j++)
                    acc[i][j] = fmaf(a[i], b[j], acc[i][j]);
        }
        __syncthreads();
    }

#pragma unroll
    for (int i = 0; i < 8; i++) {
        float* cp = C + (size_t)(m0 + ty * 8 + i) * N + n0 + tx * 8;
        *(float4*)(cp)     = make_float4(acc[i][0], acc[i][1], acc[i][2], acc[i][3]);
        *(float4*)(cp + 4) = make_float4(acc[i][4], acc[i][5], acc[i][6], acc[i][7]);
    }
}

// ---------------------------------------------------------------------------
// In-place row softmax over S[row][0..N), one block per row.
// ---------------------------------------------------------------------------
__global__ __launch_bounds__(256)
void softmax_kernel(float* __restrict__ S, int N)
{
    __shared__ float red[8];
    const int t    = threadIdx.x;
    const int lane = t & 31;
    const int wid  = t >> 5;
    float4* p4 = (float4*)(S + (size_t)blockIdx.x * N);
    const int n4 = N / 4;

    // 1) row max
    float m = -CUDART_INF_F;
    for (int i = t; i < n4; i += 256) {
        float4 vv = p4[i];
        m = fmaxf(m, fmaxf(fmaxf(vv.x, vv.y), fmaxf(vv.z, vv.w)));
    }
#pragma unroll
    for (int s = 16; s > 0; s >>= 1)
        m = fmaxf(m, __shfl_xor_sync(0xffffffffu, m, s));
    if (lane == 0) red[wid] = m;
    __syncthreads();
    m = red[0];
#pragma unroll
    for (int w = 1; w < 8; w++) m = fmaxf(m, red[w]);

    // 2) exp + sum (write back exp)
    float sum = 0.f;
    for (int i = t; i < n4; i += 256) {
        float4 vv = p4[i];
        vv.x = __expf(vv.x - m);
        vv.y = __expf(vv.y - m);
        vv.z = __expf(vv.z - m);
        vv.w = __expf(vv.w - m);
        sum += (vv.x + vv.y) + (vv.z + vv.w);
        p4[i] = vv;
    }
#pragma unroll
    for (int s = 16; s > 0; s >>= 1)
        sum += __shfl_xor_sync(0xffffffffu, sum, s);
    __syncthreads();           // red[] reuse hazard
    if (lane == 0) red[wid] = sum;
    __syncthreads();
    sum = 0.f;
#pragma unroll
    for (int w = 0; w < 8; w++) sum += red[w];
    const float inv = 1.f / sum;

    // 3) normalize
    for (int i = t; i < n4; i += 256) {
        float4 vv = p4[i];
        vv.x *= inv; vv.y *= inv; vv.z *= inv; vv.w *= inv;
        p4[i] = vv;
    }
}

// ---------------------------------------------------------------------------
extern "C" void kernel_launch(void* const* d_in, const int* in_sizes, int n_in,
                              void* d_out, int out_size)
{
    const float* q = (const float*)d_in[0];
    const float* k = (const float*)d_in[1];
    const float* v = (const float*)d_in[2];
    float* out = (float*)d_out;

    static float* S = nullptr;
    if (!S) cudaGetSymbolAddress((void**)&S, g_S);

    // K1: S = Q K^T   (M=N=4096, K=1024)
    {
        dim3 grid(NTOK / 128, NTOK / 128);
        sgemm_nt_kernel<<<grid, 256>>>(q, k, S, NTOK, NTOK, DDIM);
    }
    // K2: softmax rows of S
    {
        softmax_kernel<<<NTOK, 256>>>(S, NTOK);
    }
    // K3: out = S V   (M=4096, N=1024, K=4096)
    {
        dim3 grid(DDIM / 128, NTOK / 128);
        sgemm_nn_kernel<<<grid, 256>>>(S, v, out, NTOK, DDIM, NTOK);
    }
}

// round 15
// speedup vs baseline: 1.3094x; 1.3094x over previous
#include <cuda_runtime.h>
#include <cstdint>
#include <math_constants.h>

// out = softmax(Q K^T) V, N=4096, D=1024, fp32.
// Legacy tensor-core path (mma.sync tf32, sm_80+ baseline PTX — the harness
// lowers to plain sm_103, which rejects tcgen05/'a'-gated features).
// tf32x3 error-compensated split keeps fp32-grade accuracy.
//   K0: VT = V^T
//   K1: S  = Q K^T      (mma.sync tf32x3, 128x128x32 tiles, cp.async 3-stage)
//   K2: row softmax on S
//   K3: out = P VT^T    (same GEMM)

#define NTOK 4096
#define DDIM 1024

__device__ float g_S[(size_t)NTOK * (size_t)NTOK];   // 64 MB scores
__device__ float g_VT[(size_t)DDIM * (size_t)NTOK];  // 16 MB V^T

// ---------------------------------------------------------------------------
// helpers
// ---------------------------------------------------------------------------
__device__ __forceinline__ uint32_t smem_u32(const void* p) {
    uint32_t a;
    asm("{ .reg .u64 t; cvta.to.shared.u64 t, %1; cvt.u32.u64 %0, t; }"
        : "=r"(a) : "l"(p));
    return a;
}

__device__ __forceinline__ void cp_async16(uint32_t dst, const void* src) {
    asm volatile("cp.async.cg.shared.global [%0], [%1], 16;"
                 :: "r"(dst), "l"(src));
}
#define CP_COMMIT() asm volatile("cp.async.commit_group;" ::: "memory")
#define CP_WAIT2()  asm volatile("cp.async.wait_group 2;" ::: "memory")

__device__ __forceinline__ uint32_t f2tf(float x) {
    uint32_t u;
    asm("cvt.rna.tf32.f32 %0, %1;" : "=r"(u) : "f"(x));
    return u;
}

__device__ __forceinline__ void mma_tf32(float* c, const uint32_t* a,
                                         const uint32_t* b) {
    asm volatile(
        "mma.sync.aligned.m16n8k8.row.col.f32.tf32.tf32.f32 "
        "{%0,%1,%2,%3}, {%4,%5,%6,%7}, {%8,%9}, {%0,%1,%2,%3};"
        : "+f"(c[0]), "+f"(c[1]), "+f"(c[2]), "+f"(c[3])
        : "r"(a[0]), "r"(a[1]), "r"(a[2]), "r"(a[3]), "r"(b[0]), "r"(b[1]));
}

// ---------------------------------------------------------------------------
// C[M,N] = A[M,K] @ B[N,K]^T  (all row-major), tf32x3 via mma.sync.
// 128x128 CTA tile, BK=32, 3-stage cp.async pipeline, 256 threads (8 warps 2x4).
// ---------------------------------------------------------------------------
#define BK 32
#define AS_W 36                         // padded row stride (floats)
#define TILE_FLOATS (128 * AS_W)        // one A or B tile
#define STAGE_FLOATS (2 * TILE_FLOATS)  // A tile + B tile
#define SMEM_BYTES (3 * STAGE_FLOATS * 4)

__global__ __launch_bounds__(256, 1)
void gemm_tf32x3(const float* __restrict__ A, int lda,
                 const float* __restrict__ B, int ldb,
                 float* __restrict__ C, int ldc, int kIters)
{
    extern __shared__ float smf[];
    const uint32_t sb = smem_u32(smf);

    const int tid  = threadIdx.x;
    const int wid  = tid >> 5;
    const int lane = tid & 31;
    const int g    = lane >> 2;   // 0..7
    const int kq   = lane & 3;    // 0..3
    const int wm   = wid & 1;     // 2 m-blocks of 64
    const int wn   = wid >> 1;    // 4 n-blocks of 32
    const int m0   = blockIdx.y * 128;
    const int n0   = blockIdx.x * 128;

    // copy mapping: 4 x 16B chunks per tile per thread (128 rows x 8 chunks)
    int crow[4], ccol[4];
#pragma unroll
    for (int t = 0; t < 4; t++) {
        int idx = tid + 256 * t;   // 0..1023
        crow[t] = idx >> 3;
        ccol[t] = idx & 7;         // chunk of 4 floats
    }

    auto copy_stage = [&](int buf, int kChunk) {
        const int k0 = kChunk * BK;
        const uint32_t base = sb + (uint32_t)(buf * STAGE_FLOATS) * 4u;
#pragma unroll
        for (int t = 0; t < 4; t++) {
            uint32_t da = base + (uint32_t)(crow[t] * AS_W + ccol[t] * 4) * 4u;
            cp_async16(da, A + (size_t)(m0 + crow[t]) * lda + k0 + ccol[t] * 4);
            uint32_t db = da + (uint32_t)TILE_FLOATS * 4u;
            cp_async16(db, B + (size_t)(n0 + crow[t]) * ldb + k0 + ccol[t] * 4);
        }
    };

    float acc[4][4][4];
#pragma unroll
    for (int mt = 0; mt < 4; mt++)
#pragma unroll
        for (int nt = 0; nt < 4; nt++)
#pragma unroll
            for (int r = 0; r < 4; r++) acc[mt][nt][r] = 0.f;

    // prologue: 3 stages in flight
    copy_stage(0, 0); CP_COMMIT();
    copy_stage(1, 1); CP_COMMIT();
    copy_stage(2, 2); CP_COMMIT();

    for (int i = 0; i < kIters; i++) {
        CP_WAIT2();
        __syncthreads();

        const int s = i % 3;
        const float* As = smf + s * STAGE_FLOATS;
        const float* Bs = As + TILE_FLOATS;

#pragma unroll
        for (int k8 = 0; k8 < BK / 8; k8++) {
            const int kc = k8 * 8 + kq;

            uint32_t Ahi[4][4], Alo[4][4];
#pragma unroll
            for (int mt = 0; mt < 4; mt++) {
                const int r0 = wm * 64 + mt * 16 + g;
                const int r1 = r0 + 8;
                float x0 = As[r0 * AS_W + kc];
                float x1 = As[r1 * AS_W + kc];
                float x2 = As[r0 * AS_W + kc + 4];
                float x3 = As[r1 * AS_W + kc + 4];
                Ahi[mt][0] = f2tf(x0); Alo[mt][0] = f2tf(x0 - __uint_as_float(Ahi[mt][0]));
                Ahi[mt][1] = f2tf(x1); Alo[mt][1] = f2tf(x1 - __uint_as_float(Ahi[mt][1]));
                Ahi[mt][2] = f2tf(x2); Alo[mt][2] = f2tf(x2 - __uint_as_float(Ahi[mt][2]));
                Ahi[mt][3] = f2tf(x3); Alo[mt][3] = f2tf(x3 - __uint_as_float(Ahi[mt][3]));
            }
            uint32_t Bhi[4][2], Blo[4][2];
#pragma unroll
            for (int nt = 0; nt < 4; nt++) {
                const int n = wn * 32 + nt * 8 + g;
                float y0 = Bs[n * AS_W + kc];
                float y1 = Bs[n * AS_W + kc + 4];
                Bhi[nt][0] = f2tf(y0); Blo[nt][0] = f2tf(y0 - __uint_as_float(Bhi[nt][0]));
                Bhi[nt][1] = f2tf(y1); Blo[nt][1] = f2tf(y1 - __uint_as_float(Bhi[nt][1]));
            }
#pragma unroll
            for (int mt = 0; mt < 4; mt++)
#pragma unroll
                for (int nt = 0; nt < 4; nt++) {
                    mma_tf32(acc[mt][nt], Ahi[mt], Bhi[nt]);
                    mma_tf32(acc[mt][nt], Ahi[mt], Blo[nt]);
                    mma_tf32(acc[mt][nt], Alo[mt], Bhi[nt]);
                }
        }

        __syncthreads();
        if (i + 3 < kIters) copy_stage(s, i + 3);
        CP_COMMIT();   // empty group when no copy — keeps wait_group bookkeeping exact
    }

    // epilogue
#pragma unroll
    for (int mt = 0; mt < 4; mt++) {
        const int r0 = m0 + wm * 64 + mt * 16 + g;
#pragma unroll
        for (int nt = 0; nt < 4; nt++) {
            const int col = n0 + wn * 32 + nt * 8 + kq * 2;
            float2 v0 = make_float2(acc[mt][nt][0], acc[mt][nt][1]);
            float2 v1 = make_float2(acc[mt][nt][2], acc[mt][nt][3]);
            *(float2*)(C + (size_t)r0 * ldc + col)       = v0;
            *(float2*)(C + (size_t)(r0 + 8) * ldc + col) = v1;
        }
    }
}

// ---------------------------------------------------------------------------
// VT[c][r] = V[r][c]
// ---------------------------------------------------------------------------
__global__ __launch_bounds__(256)
void transpose_kernel(const float* __restrict__ in, float* __restrict__ out,
                      int R, int Ccols)
{
    __shared__ float t[32][33];
    const int r0 = blockIdx.y * 32, c0 = blockIdx.x * 32;
    const int x = threadIdx.x & 31, y = threadIdx.x >> 5;
#pragma unroll
    for (int i = 0; i < 32; i += 8)
        t[y + i][x] = in[(size_t)(r0 + y + i) * Ccols + c0 + x];
    __syncthreads();
#pragma unroll
    for (int i = 0; i < 32; i += 8)
        out[(size_t)(c0 + y + i) * R + r0 + x] = t[x][y + i];
}

// ---------------------------------------------------------------------------
// In-place row softmax, one block per row.
// ---------------------------------------------------------------------------
__global__ __launch_bounds__(256)
void softmax_kernel(float* __restrict__ S, int N)
{
    __shared__ float red[8];
    const int t    = threadIdx.x;
    const int lane = t & 31;
    const int wid  = t >> 5;
    float4* p4 = (float4*)(S + (size_t)blockIdx.x * N);
    const int n4 = N / 4;

    float m = -CUDART_INF_F;
    for (int i = t; i < n4; i += 256) {
        float4 vv = p4[i];
        m = fmaxf(m, fmaxf(fmaxf(vv.x, vv.y), fmaxf(vv.z, vv.w)));
    }
#pragma unroll
    for (int s = 16; s > 0; s >>= 1)
        m = fmaxf(m, __shfl_xor_sync(0xffffffffu, m, s));
    if (lane == 0) red[wid] = m;
    __syncthreads();
    m = red[0];
#pragma unroll
    for (int w = 1; w < 8; w++) m = fmaxf(m, red[w]);

    float sum = 0.f;
    for (int i = t; i < n4; i += 256) {
        float4 vv = p4[i];
        vv.x = __expf(vv.x - m);
        vv.y = __expf(vv.y - m);
        vv.z = __expf(vv.z - m);
        vv.w = __expf(vv.w - m);
        sum += (vv.x + vv.y) + (vv.z + vv.w);
        p4[i] = vv;
    }
#pragma unroll
    for (int s = 16; s > 0; s >>= 1)
        sum += __shfl_xor_sync(0xffffffffu, sum, s);
    __syncthreads();
    if (lane == 0) red[wid] = sum;
    __syncthreads();
    sum = 0.f;
#pragma unroll
    for (int w = 0; w < 8; w++) sum += red[w];
    const float inv = 1.f / sum;

    for (int i = t; i < n4; i += 256) {
        float4 vv = p4[i];
        vv.x *= inv; vv.y *= inv; vv.z *= inv; vv.w *= inv;
        p4[i] = vv;
    }
}

// ---------------------------------------------------------------------------
extern "C" void kernel_launch(void* const* d_in, const int* in_sizes, int n_in,
                              void* d_out, int out_size)
{
    const float* q = (const float*)d_in[0];
    const float* k = (const float*)d_in[1];
    const float* v = (const float*)d_in[2];
    float* out = (float*)d_out;

    static float* S  = nullptr;
    static float* VT = nullptr;
    static bool init = false;
    if (!init) {
        cudaGetSymbolAddress((void**)&S, g_S);
        cudaGetSymbolAddress((void**)&VT, g_VT);
        cudaFuncSetAttribute(gemm_tf32x3,
                             cudaFuncAttributeMaxDynamicSharedMemorySize, SMEM_BYTES);
        init = true;
    }

    // K0: VT = V^T
    {
        dim3 grid(DDIM / 32, NTOK / 32);
        transpose_kernel<<<grid, 256>>>(v, VT, NTOK, DDIM);
    }
    // K1: S = Q K^T   (M=N=4096, K=1024 -> 32 k-iters)
    {
        dim3 grid(NTOK / 128, NTOK / 128);
        gemm_tf32x3<<<grid, 256, SMEM_BYTES>>>(q, DDIM, k, DDIM, S, NTOK, DDIM / BK);
    }
    // K2: softmax rows of S
    softmax_kernel<<<NTOK, 256>>>(S, NTOK);
    // K3: out = P VT^T  (M=4096, N=1024, K=4096 -> 128 k-iters)
    {
        dim3 grid(DDIM / 128, NTOK / 128);
        gemm_tf32x3<<<grid, 256, SMEM_BYTES>>>(S, NTOK, VT, NTOK, out, DDIM, NTOK / BK);
    }
}